// round 15
// baseline (speedup 1.0000x reference)
#include <cuda_runtime.h>
#include <cfloat>

#define VOCAB   50257
#define BEAM    8
#define BSZ     64
#define K       16
#define NGRAM   4
#define STEPDIM 16
#define T       512
#define NW      (T / 32)      // 16 warps

typedef unsigned long long ull;

// Monotone float -> uint32 encode: a > b  <=>  enc(a) > enc(b)
__device__ __forceinline__ unsigned enc_f32(float v) {
    unsigned u = __float_as_uint(v);
    return (u & 0x80000000u) ? ~u : (u | 0x80000000u);
}
// Key = [enc(value):32 | ~flat_index:32]: bigger = bigger value, then smaller
// flat index (lax.top_k stable tie-break). Unique per row.
__device__ __forceinline__ ull make_key_enc(unsigned ev, unsigned flat) {
    return ((ull)ev << 32) | (unsigned)(~flat);
}

// Sort a bitonic 16-sequence descending (static indexing -> registers).
__device__ __forceinline__ void bitonic16_desc(ull v[K]) {
    #pragma unroll
    for (int d = 8; d >= 1; d >>= 1) {
        #pragma unroll
        for (int i = 0; i < K; i++) {
            if ((i & d) == 0) {
                ull a = v[i], b = v[i | d];
                v[i]     = a > b ? a : b;
                v[i | d] = a > b ? b : a;
            }
        }
    }
}
// Merge own sorted-desc 16-list with xor-partner's -> top-16 of union, desc.
__device__ __forceinline__ void warp_merge_round(ull v[K], int o) {
    ull other[K];
    #pragma unroll
    for (int i = 0; i < K; i++)
        other[i] = __shfl_xor_sync(0xffffffffu, v[K - 1 - i], o);
    #pragma unroll
    for (int i = 0; i < K; i++)
        v[i] = v[i] > other[i] ? v[i] : other[i];
    bitonic16_desc(v);
}
// Unrolled insert into sorted-desc 16-list (registers only).
__device__ __forceinline__ void insert16(ull best[K], ull key) {
    ull x = key;
    #pragma unroll
    for (int j = 0; j < K; j++) {
        ull mx = best[j] > x ? best[j] : x;
        ull mn = best[j] > x ? x : best[j];
        best[j] = mx;
        x = mn;
    }
}
__device__ __forceinline__ ull select_lane(const ull v[K], int lane) {
    ull r = v[0];
    #pragma unroll
    for (int j = 1; j < K; j++) if (lane == j) r = v[j];
    return r;
}
// Exact candidate insert (value bias-applied exactly as reference computes).
__device__ __forceinline__ void cand(ull best[K], unsigned &curmin_hi,
                                     float v, unsigned flat) {
    unsigned e = enc_f32(v);
    if (e > curmin_hi) {   // equal value -> later index loses: skip is exact
        insert16(best, make_key_enc(e, flat));
        curmin_hi = (unsigned)(best[K - 1] >> 32);
    }
}

__global__ __launch_bounds__(T, 1) void beam_topk(
    const float* __restrict__ lprobs,
    const float* __restrict__ scores,
    const int*   __restrict__ mask,
    const int*   __restrict__ step_ptr,
    float*       __restrict__ out)
{
    const int row  = blockIdx.x;
    const int tid  = threadIdx.x;
    const int warp = tid >> 5, lane = tid & 31;
    const int step = step_ptr ? step_ptr[0] : STEPDIM;
    const int nbeam = (step == 0) ? 1 : BEAM;

    __shared__ float s_wmax[NW];
    __shared__ float s_bias[BEAM];
    __shared__ int   s_keep;

    if (tid < BEAM) {
        const int bb = row * BEAM + tid;
        const int4 mm = ((const int4*)mask)[bb];
        const bool kp = (mm.x + mm.y + mm.z + mm.w) == NGRAM;
        unsigned bal = __ballot_sync(0xffu, kp);
        if (tid == 0) s_keep = (int)bal;
        s_bias[tid] = (step == 0) ? 0.0f : scores[bb * STEPDIM + (step - 1)];
    }
    __syncthreads();
    const int keepmask = s_keep;

    // Per-thread top-16 across ALL beams of this row (keys globally ordered).
    ull best[K];
    #pragma unroll
    for (int i = 0; i < K; i++) best[i] = 0ull;
    unsigned curmin_hi = 0u;

    for (int b = 0; b < nbeam; b++) {
        const float bias = s_bias[b];
        const unsigned flatbase = (unsigned)b * VOCAB;

        if (!((keepmask >> b) & 1)) {
            // Non-kept beam is constant (= bias): top-16 = first 16 indices.
            if (tid < K)
                cand(best, curmin_hi, bias, flatbase + (unsigned)tid);
            continue;
        }

        const int bb = row * BEAM + b;
        const float* lp = lprobs + (size_t)bb * VOCAB;
        const int pad  = (4 - (bb & 3)) & 3;     // align float4 (VOCAB%4==1)
        const float4* fp4 = (const float4*)(lp + pad);
        const int nq   = (VOCAB - pad) >> 2;
        const int tail = VOCAB - pad - 4 * nq;

        // ---- pass A: per-thread raw max, 4x unrolled (MLP=4) ----
        float t0 = -FLT_MAX, t1 = -FLT_MAX, t2 = -FLT_MAX, t3 = -FLT_MAX;
        if (tid < pad)  t0 = lp[tid];
        if (tid < tail) t0 = fmaxf(t0, lp[pad + 4 * nq + tid]);
        int q = tid;
        for (; q + 3 * T < nq; q += 4 * T) {
            float4 a = fp4[q];
            float4 c = fp4[q + T];
            float4 d = fp4[q + 2 * T];
            float4 e = fp4[q + 3 * T];
            t0 = fmaxf(t0, fmaxf(fmaxf(a.x, a.y), fmaxf(a.z, a.w)));
            t1 = fmaxf(t1, fmaxf(fmaxf(c.x, c.y), fmaxf(c.z, c.w)));
            t2 = fmaxf(t2, fmaxf(fmaxf(d.x, d.y), fmaxf(d.z, d.w)));
            t3 = fmaxf(t3, fmaxf(fmaxf(e.x, e.y), fmaxf(e.z, e.w)));
        }
        for (; q < nq; q += T) {
            float4 a = fp4[q];
            t0 = fmaxf(t0, fmaxf(fmaxf(a.x, a.y), fmaxf(a.z, a.w)));
        }
        const float tm = fmaxf(fmaxf(t0, t1), fmaxf(t2, t3));

        float wm = tm;
        #pragma unroll
        for (int o = 16; o > 0; o >>= 1)
            wm = fmaxf(wm, __shfl_xor_sync(0xffffffffu, wm, o));
        if (lane == 0) s_wmax[warp] = wm;
        __syncthreads();
        // m = min of 16 warp maxes: >=16 distinct elements >= m  =>  m <= v16
        float m = s_wmax[0];
        #pragma unroll
        for (int w = 1; w < NW; w++) m = fminf(m, s_wmax[w]);
        __syncthreads();    // s_wmax reused next beam

        // ---- pass B: only threads whose exact max clears m re-stream ----
        const bool act = (tm >= m);
        if (__any_sync(0xffffffffu, act)) {
            if (act) {
                if (tid < pad && lp[tid] >= m)
                    cand(best, curmin_hi, lp[tid] + bias, flatbase + tid);
                if (tid < tail) {
                    const int idx = pad + 4 * nq + tid;
                    if (lp[idx] >= m)
                        cand(best, curmin_hi, lp[idx] + bias, flatbase + idx);
                }
                int p = tid;
                for (; p + 3 * T < nq; p += 4 * T) {
                    float4 a = fp4[p];
                    float4 c = fp4[p + T];
                    float4 d = fp4[p + 2 * T];
                    float4 e = fp4[p + 3 * T];
                    const unsigned bi = flatbase + (unsigned)(pad + 4 * p);
                    if (fmaxf(fmaxf(a.x, a.y), fmaxf(a.z, a.w)) >= m) {
                        if (a.x >= m) cand(best, curmin_hi, a.x + bias, bi);
                        if (a.y >= m) cand(best, curmin_hi, a.y + bias, bi + 1);
                        if (a.z >= m) cand(best, curmin_hi, a.z + bias, bi + 2);
                        if (a.w >= m) cand(best, curmin_hi, a.w + bias, bi + 3);
                    }
                    if (fmaxf(fmaxf(c.x, c.y), fmaxf(c.z, c.w)) >= m) {
                        const unsigned b1 = bi + 4 * T;
                        if (c.x >= m) cand(best, curmin_hi, c.x + bias, b1);
                        if (c.y >= m) cand(best, curmin_hi, c.y + bias, b1 + 1);
                        if (c.z >= m) cand(best, curmin_hi, c.z + bias, b1 + 2);
                        if (c.w >= m) cand(best, curmin_hi, c.w + bias, b1 + 3);
                    }
                    if (fmaxf(fmaxf(d.x, d.y), fmaxf(d.z, d.w)) >= m) {
                        const unsigned b2 = bi + 8 * T;
                        if (d.x >= m) cand(best, curmin_hi, d.x + bias, b2);
                        if (d.y >= m) cand(best, curmin_hi, d.y + bias, b2 + 1);
                        if (d.z >= m) cand(best, curmin_hi, d.z + bias, b2 + 2);
                        if (d.w >= m) cand(best, curmin_hi, d.w + bias, b2 + 3);
                    }
                    if (fmaxf(fmaxf(e.x, e.y), fmaxf(e.z, e.w)) >= m) {
                        const unsigned b3 = bi + 12 * T;
                        if (e.x >= m) cand(best, curmin_hi, e.x + bias, b3);
                        if (e.y >= m) cand(best, curmin_hi, e.y + bias, b3 + 1);
                        if (e.z >= m) cand(best, curmin_hi, e.z + bias, b3 + 2);
                        if (e.w >= m) cand(best, curmin_hi, e.w + bias, b3 + 3);
                    }
                }
                for (; p < nq; p += T) {
                    float4 a = fp4[p];
                    if (fmaxf(fmaxf(a.x, a.y), fmaxf(a.z, a.w)) >= m) {
                        const unsigned bi = flatbase + (unsigned)(pad + 4 * p);
                        if (a.x >= m) cand(best, curmin_hi, a.x + bias, bi);
                        if (a.y >= m) cand(best, curmin_hi, a.y + bias, bi + 1);
                        if (a.z >= m) cand(best, curmin_hi, a.z + bias, bi + 2);
                        if (a.w >= m) cand(best, curmin_hi, a.w + bias, bi + 3);
                    }
                }
            }
        }
    }

    // ---- final: 512 lists -> 16 warp lists -> 1 block list ----
    warp_merge_round(best, 1);
    warp_merge_round(best, 2);
    warp_merge_round(best, 4);
    warp_merge_round(best, 8);
    warp_merge_round(best, 16);

    __shared__ ull s_lists[NW * K];
    if (lane == 0) {
        #pragma unroll
        for (int qq = 0; qq < K; qq++) s_lists[warp * K + qq] = best[qq];
    }
    __syncthreads();

    if (warp == 0) {
        ull v[K];
        const int src = lane & 15;
        #pragma unroll
        for (int qq = 0; qq < K; qq++) v[qq] = s_lists[src * K + qq];
        warp_merge_round(v, 1);
        warp_merge_round(v, 2);
        warp_merge_round(v, 4);
        warp_merge_round(v, 8);

        if (lane < K) {
            ull key = select_lane(v, lane);
            unsigned hi = (unsigned)(key >> 32);
            unsigned lo = (unsigned)key;
            unsigned u  = (hi & 0x80000000u) ? (hi ^ 0x80000000u) : ~hi;
            float val = __uint_as_float(u);
            unsigned flat = ~lo;
            unsigned bsel = flat / VOCAB;
            unsigned vsel = flat - bsel * VOCAB;

            out[              row * K + lane] = val;           // scores_buf
            out[BSZ * K     + row * K + lane] = (float)vsel;   // indices_buf
            out[2 * BSZ * K + row * K + lane] = (float)bsel;   // beams_buf
        }
    }
}

extern "C" void kernel_launch(void* const* d_in, const int* in_sizes, int n_in,
                              void* d_out, int out_size) {
    (void)in_sizes; (void)out_size;
    const float* lprobs = (const float*)d_in[0];
    const float* scores = (const float*)d_in[1];
    const int*   mask   = (const int*)d_in[2];
    const int*   step   = (n_in > 3) ? (const int*)d_in[3] : nullptr;

    beam_topk<<<BSZ, T>>>(lprobs, scores, mask, step, (float*)d_out);
}

// round 16
// speedup vs baseline: 1.0500x; 1.0500x over previous
#include <cuda_runtime.h>
#include <cfloat>

#define VOCAB   50257
#define BEAM    8
#define BSZ     64
#define K       16
#define NGRAM   4
#define STEPDIM 16
#define T       512
#define NW      (T / 32)      // 16 warps

typedef unsigned long long ull;

// Monotone float -> uint32 encode: a > b  <=>  enc(a) > enc(b)
__device__ __forceinline__ unsigned enc_f32(float v) {
    unsigned u = __float_as_uint(v);
    return (u & 0x80000000u) ? ~u : (u | 0x80000000u);
}
// Key = [enc(value):32 | ~flat_index:32]: bigger = bigger value, then smaller
// flat index (lax.top_k stable tie-break). Unique per row.
__device__ __forceinline__ ull make_key_enc(unsigned ev, unsigned flat) {
    return ((ull)ev << 32) | (unsigned)(~flat);
}

// Sort a bitonic 16-sequence descending (static indexing -> registers).
__device__ __forceinline__ void bitonic16_desc(ull v[K]) {
    #pragma unroll
    for (int d = 8; d >= 1; d >>= 1) {
        #pragma unroll
        for (int i = 0; i < K; i++) {
            if ((i & d) == 0) {
                ull a = v[i], b = v[i | d];
                v[i]     = a > b ? a : b;
                v[i | d] = a > b ? b : a;
            }
        }
    }
}
// Merge own sorted-desc 16-list with xor-partner's -> top-16 of union, desc.
__device__ __forceinline__ void warp_merge_round(ull v[K], int o) {
    ull other[K];
    #pragma unroll
    for (int i = 0; i < K; i++)
        other[i] = __shfl_xor_sync(0xffffffffu, v[K - 1 - i], o);
    #pragma unroll
    for (int i = 0; i < K; i++)
        v[i] = v[i] > other[i] ? v[i] : other[i];
    bitonic16_desc(v);
}
// Unrolled insert into sorted-desc 16-list (registers only).
__device__ __forceinline__ void insert16(ull best[K], ull key) {
    ull x = key;
    #pragma unroll
    for (int j = 0; j < K; j++) {
        ull mx = best[j] > x ? best[j] : x;
        ull mn = best[j] > x ? x : best[j];
        best[j] = mx;
        x = mn;
    }
}
__device__ __forceinline__ ull select_lane(const ull v[K], int lane) {
    ull r = v[0];
    #pragma unroll
    for (int j = 1; j < K; j++) if (lane == j) r = v[j];
    return r;
}
// Exact candidate insert (value bias-applied exactly as reference computes).
__device__ __forceinline__ void cand(ull best[K], unsigned &curmin_hi,
                                     float v, unsigned flat) {
    unsigned e = enc_f32(v);
    if (e > curmin_hi) {   // equal value -> later index loses: skip is exact
        insert16(best, make_key_enc(e, flat));
        curmin_hi = (unsigned)(best[K - 1] >> 32);
    }
}

__global__ __launch_bounds__(T, 1) void beam_topk(
    const float* __restrict__ lprobs,
    const float* __restrict__ scores,
    const int*   __restrict__ mask,
    const int*   __restrict__ step_ptr,
    float*       __restrict__ out)
{
    const int row  = blockIdx.x;
    const int tid  = threadIdx.x;
    const int warp = tid >> 5, lane = tid & 31;
    const int step = step_ptr ? step_ptr[0] : STEPDIM;
    const int nbeam = (step == 0) ? 1 : BEAM;

    __shared__ float s_wmax[NW][BEAM];
    __shared__ float s_bias[BEAM];
    __shared__ int   s_keep;
    __shared__ int   s_kb[BEAM];     // compacted kept beam ids
    __shared__ int   s_nk;

    if (tid < BEAM) {
        const int bb = row * BEAM + tid;
        const int4 mm = ((const int4*)mask)[bb];
        const bool kp = ((mm.x + mm.y + mm.z + mm.w) == NGRAM) && (tid < nbeam);
        unsigned bal = __ballot_sync(0xffu, kp);
        if (tid == 0) {
            s_keep = (int)bal;
            s_nk = __popc(bal);
        }
        if (kp) s_kb[__popc(bal & ((1u << tid) - 1u))] = tid;
        s_bias[tid] = (step == 0) ? 0.0f : scores[bb * STEPDIM + (step - 1)];
    }
    __syncthreads();
    const int keepmask = s_keep;
    const int nk = s_nk;

    // Per-thread top-16 across ALL beams of this row (keys globally ordered).
    ull best[K];
    #pragma unroll
    for (int i = 0; i < K; i++) best[i] = 0ull;
    unsigned curmin_hi = 0u;

    // Non-kept beams are constant (= bias): top-16 = first 16 indices.
    #pragma unroll
    for (int b = 0; b < BEAM; b++) {
        if (b < nbeam && !((keepmask >> b) & 1) && tid < K)
            cand(best, curmin_hi, s_bias[b], (unsigned)b * VOCAB + (unsigned)tid);
    }

    // Per-kept-beam state (static-indexed register arrays).
    const float4* fp4j[BEAM];
    int padj[BEAM], nqj[BEAM];
    float tmj[BEAM];
    #pragma unroll
    for (int j = 0; j < BEAM; j++) {
        fp4j[j] = nullptr; padj[j] = 0; nqj[j] = 0; tmj[j] = -FLT_MAX;
        if (j < nk) {
            const int bb = row * BEAM + s_kb[j];
            const float* lp = lprobs + (size_t)bb * VOCAB;
            const int pad = (4 - (bb & 3)) & 3;     // float4 align (VOCAB%4==1)
            padj[j] = pad;
            fp4j[j] = (const float4*)(lp + pad);
            nqj[j]  = (VOCAB - pad) >> 2;
        }
    }

    // ---- pass A (fused): one float4 load per kept beam per iteration ----
    // Independent streams across beams -> MLP = nk without manual unrolling.
    {
        // prologue: pad prefix + tail elements, per beam
        #pragma unroll
        for (int j = 0; j < BEAM; j++) {
            if (j < nk) {
                const float* lp = (const float*)fp4j[j] - padj[j];
                if (tid < padj[j]) tmj[j] = lp[tid];
                const int tail = VOCAB - padj[j] - 4 * nqj[j];
                if (tid < tail)
                    tmj[j] = fmaxf(tmj[j], lp[padj[j] + 4 * nqj[j] + tid]);
            }
        }
        const int nqmax = (nk > 0) ? nqj[0] + 1 : 0;   // nq varies by <=1
        for (int q = tid; q < nqmax; q += T) {
            #pragma unroll
            for (int j = 0; j < BEAM; j++) {
                if (j < nk && q < nqj[j]) {
                    float4 a = fp4j[j][q];
                    tmj[j] = fmaxf(tmj[j],
                                   fmaxf(fmaxf(a.x, a.y), fmaxf(a.z, a.w)));
                }
            }
        }
    }

    // per-beam warp max -> shared -> per-beam threshold m_j
    #pragma unroll
    for (int j = 0; j < BEAM; j++) {
        if (j < nk) {
            float wm = tmj[j];
            #pragma unroll
            for (int o = 16; o > 0; o >>= 1)
                wm = fmaxf(wm, __shfl_xor_sync(0xffffffffu, wm, o));
            if (lane == 0) s_wmax[warp][j] = wm;
        }
    }
    __syncthreads();

    // ---- pass B: per beam, only threads whose exact max clears m_j ----
    #pragma unroll
    for (int j = 0; j < BEAM; j++) {
        if (j < nk) {
            // m_j = min of 16 warp maxes: >=16 elements >= m  =>  m <= v16
            float m = s_wmax[0][j];
            #pragma unroll
            for (int w = 1; w < NW; w++) m = fminf(m, s_wmax[w][j]);

            const bool act = (tmj[j] >= m);
            if (__any_sync(0xffffffffu, act) && act) {
                const int b = s_kb[j];
                const float bias = s_bias[b];
                const unsigned flatbase = (unsigned)b * VOCAB;
                const float* lp = (const float*)fp4j[j] - padj[j];
                const int pad = padj[j], nq = nqj[j];
                const int tail = VOCAB - pad - 4 * nq;

                if (tid < pad && lp[tid] >= m)
                    cand(best, curmin_hi, lp[tid] + bias, flatbase + tid);
                if (tid < tail) {
                    const int idx = pad + 4 * nq + tid;
                    if (lp[idx] >= m)
                        cand(best, curmin_hi, lp[idx] + bias, flatbase + idx);
                }
                for (int q = tid; q < nq; q += T) {
                    float4 a = fp4j[j][q];
                    if (fmaxf(fmaxf(a.x, a.y), fmaxf(a.z, a.w)) >= m) {
                        const unsigned bi = flatbase + (unsigned)(pad + 4 * q);
                        if (a.x >= m) cand(best, curmin_hi, a.x + bias, bi);
                        if (a.y >= m) cand(best, curmin_hi, a.y + bias, bi + 1);
                        if (a.z >= m) cand(best, curmin_hi, a.z + bias, bi + 2);
                        if (a.w >= m) cand(best, curmin_hi, a.w + bias, bi + 3);
                    }
                }
            }
        }
    }

    // ---- final: 512 lists -> 16 warp lists -> 1 block list ----
    warp_merge_round(best, 1);
    warp_merge_round(best, 2);
    warp_merge_round(best, 4);
    warp_merge_round(best, 8);
    warp_merge_round(best, 16);

    __shared__ ull s_lists[NW * K];
    if (lane == 0) {
        #pragma unroll
        for (int qq = 0; qq < K; qq++) s_lists[warp * K + qq] = best[qq];
    }
    __syncthreads();

    if (warp == 0) {
        ull v[K];
        const int src = lane & 15;
        #pragma unroll
        for (int qq = 0; qq < K; qq++) v[qq] = s_lists[src * K + qq];
        warp_merge_round(v, 1);
        warp_merge_round(v, 2);
        warp_merge_round(v, 4);
        warp_merge_round(v, 8);

        if (lane < K) {
            ull key = select_lane(v, lane);
            unsigned hi = (unsigned)(key >> 32);
            unsigned lo = (unsigned)key;
            unsigned u  = (hi & 0x80000000u) ? (hi ^ 0x80000000u) : ~hi;
            float val = __uint_as_float(u);
            unsigned flat = ~lo;
            unsigned bsel = flat / VOCAB;
            unsigned vsel = flat - bsel * VOCAB;

            out[              row * K + lane] = val;           // scores_buf
            out[BSZ * K     + row * K + lane] = (float)vsel;   // indices_buf
            out[2 * BSZ * K + row * K + lane] = (float)bsel;   // beams_buf
        }
    }
}

extern "C" void kernel_launch(void* const* d_in, const int* in_sizes, int n_in,
                              void* d_out, int out_size) {
    (void)in_sizes; (void)out_size;
    const float* lprobs = (const float*)d_in[0];
    const float* scores = (const float*)d_in[1];
    const int*   mask   = (const int*)d_in[2];
    const int*   step   = (n_in > 3) ? (const int*)d_in[3] : nullptr;

    beam_topk<<<BSZ, T>>>(lprobs, scores, mask, step, (float*)d_out);
}

// round 17
// speedup vs baseline: 1.3493x; 1.2851x over previous
#include <cuda_runtime.h>
#include <cfloat>

#define VOCAB   50257
#define BEAM    8
#define BSZ     64
#define K       16
#define NGRAM   4
#define STEPDIM 16
#define T       512
#define NW      (T / 32)      // 16 warps

typedef unsigned long long ull;

// Per-beam exact top-16 lists: [bb][q], sorted descending by key.
__device__ ull      g_scratch[BSZ * BEAM * K];
__device__ unsigned g_count[BSZ];     // zero-init; reset after each use (graph-safe)

// Monotone float -> uint32 encode: a > b  <=>  enc(a) > enc(b)
__device__ __forceinline__ unsigned enc_f32(float v) {
    unsigned u = __float_as_uint(v);
    return (u & 0x80000000u) ? ~u : (u | 0x80000000u);
}
// Key = [enc(value):32 | ~flat_index:32]: bigger = bigger value, then smaller
// flat index (lax.top_k stable tie-break). Unique per row.
__device__ __forceinline__ ull make_key_enc(unsigned ev, unsigned flat) {
    return ((ull)ev << 32) | (unsigned)(~flat);
}

// Sort a bitonic 16-sequence descending (static indexing -> registers).
__device__ __forceinline__ void bitonic16_desc(ull v[K]) {
    #pragma unroll
    for (int d = 8; d >= 1; d >>= 1) {
        #pragma unroll
        for (int i = 0; i < K; i++) {
            if ((i & d) == 0) {
                ull a = v[i], b = v[i | d];
                v[i]     = a > b ? a : b;
                v[i | d] = a > b ? b : a;
            }
        }
    }
}
// Merge own sorted-desc 16-list with xor-partner's -> top-16 of union, desc.
__device__ __forceinline__ void warp_merge_round(ull v[K], int o) {
    ull other[K];
    #pragma unroll
    for (int i = 0; i < K; i++)
        other[i] = __shfl_xor_sync(0xffffffffu, v[K - 1 - i], o);
    #pragma unroll
    for (int i = 0; i < K; i++)
        v[i] = v[i] > other[i] ? v[i] : other[i];
    bitonic16_desc(v);
}
// Unrolled insert into sorted-desc 16-list (registers only).
__device__ __forceinline__ void insert16(ull best[K], ull key) {
    ull x = key;
    #pragma unroll
    for (int j = 0; j < K; j++) {
        ull mx = best[j] > x ? best[j] : x;
        ull mn = best[j] > x ? x : best[j];
        best[j] = mx;
        x = mn;
    }
}
__device__ __forceinline__ ull select_lane(const ull v[K], int lane) {
    ull r = v[0];
    #pragma unroll
    for (int j = 1; j < K; j++) if (lane == j) r = v[j];
    return r;
}
// Exact candidate insert (value bias-applied exactly as reference computes).
__device__ __forceinline__ void cand(ull best[K], unsigned &curmin_hi,
                                     float v, unsigned flat) {
    unsigned e = enc_f32(v);
    if (e > curmin_hi) {   // equal value -> later index loses: skip is exact
        insert16(best, make_key_enc(e, flat));
        curmin_hi = (unsigned)(best[K - 1] >> 32);
    }
}

__global__ __launch_bounds__(T, 1) void beam_topk(
    const float* __restrict__ lprobs,
    const float* __restrict__ scores,
    const int*   __restrict__ mask,
    const int*   __restrict__ step_ptr,
    float*       __restrict__ out)
{
    const int bb   = blockIdx.x;           // row*8 + beam
    const int row  = bb >> 3, beam = bb & 7;
    const int tid  = threadIdx.x;
    const int warp = tid >> 5, lane = tid & 31;
    const int step = step_ptr ? step_ptr[0] : STEPDIM;
    const bool valid = !(step == 0 && beam != 0);

    __shared__ float s_wmax[NW];
    __shared__ ull   s_lists[NW * K];
    __shared__ int   s_keep, s_last;
    __shared__ float s_bias;

    if (tid == 0) {
        const int4 mm = ((const int4*)mask)[bb];
        s_keep = ((mm.x + mm.y + mm.z + mm.w) == NGRAM);
        s_bias = (step == 0) ? 0.0f : scores[bb * STEPDIM + (step - 1)];
    }
    __syncthreads();

    // ================= scan phase: this block's beam (if kept) =================
    if (valid && s_keep) {
        const float bias = s_bias;
        const unsigned flatbase = (unsigned)beam * VOCAB;
        const float* lp = lprobs + (size_t)bb * VOCAB;
        const int pad  = (4 - (bb & 3)) & 3;     // float4 align (VOCAB%4==1)
        const float4* fp4 = (const float4*)(lp + pad);
        const int nq   = (VOCAB - pad) >> 2;
        const int tail = VOCAB - pad - 4 * nq;

        // ---- pass A: per-thread raw max (plain loop: let ptxas batch) ----
        float tm = -FLT_MAX;
        if (tid < pad)  tm = lp[tid];
        if (tid < tail) tm = fmaxf(tm, lp[pad + 4 * nq + tid]);
        for (int q = tid; q < nq; q += T) {
            float4 a = fp4[q];
            tm = fmaxf(tm, fmaxf(fmaxf(a.x, a.y), fmaxf(a.z, a.w)));
        }
        float wm = tm;
        #pragma unroll
        for (int o = 16; o > 0; o >>= 1)
            wm = fmaxf(wm, __shfl_xor_sync(0xffffffffu, wm, o));
        if (lane == 0) s_wmax[warp] = wm;
        __syncthreads();
        // m = min of 16 warp maxes: >=16 distinct elements >= m  =>  m <= v16
        float m = s_wmax[0];
        #pragma unroll
        for (int w = 1; w < NW; w++) m = fminf(m, s_wmax[w]);

        // ---- pass B: only threads whose exact max clears m (L2-hot) ----
        ull best[K];
        #pragma unroll
        for (int i = 0; i < K; i++) best[i] = 0ull;
        unsigned curmin_hi = 0u;

        const bool act = (tm >= m);
        if (__any_sync(0xffffffffu, act) && act) {
            if (tid < pad && lp[tid] >= m)
                cand(best, curmin_hi, lp[tid] + bias, flatbase + tid);
            if (tid < tail) {
                const int idx = pad + 4 * nq + tid;
                if (lp[idx] >= m)
                    cand(best, curmin_hi, lp[idx] + bias, flatbase + idx);
            }
            for (int q = tid; q < nq; q += T) {
                float4 a = fp4[q];
                if (fmaxf(fmaxf(a.x, a.y), fmaxf(a.z, a.w)) >= m) {
                    const unsigned bi = flatbase + (unsigned)(pad + 4 * q);
                    if (a.x >= m) cand(best, curmin_hi, a.x + bias, bi);
                    if (a.y >= m) cand(best, curmin_hi, a.y + bias, bi + 1);
                    if (a.z >= m) cand(best, curmin_hi, a.z + bias, bi + 2);
                    if (a.w >= m) cand(best, curmin_hi, a.w + bias, bi + 3);
                }
            }
        }

        // ---- block reduce: 512 lists -> beam's exact top-16 ----
        warp_merge_round(best, 1);
        warp_merge_round(best, 2);
        warp_merge_round(best, 4);
        warp_merge_round(best, 8);
        warp_merge_round(best, 16);
        if (lane == 0) {
            #pragma unroll
            for (int q = 0; q < K; q++) s_lists[warp * K + q] = best[q];
        }
        __syncthreads();
        if (warp == 0) {
            ull v[K];
            const int src = lane & 15;
            #pragma unroll
            for (int q = 0; q < K; q++) v[q] = s_lists[src * K + q];
            warp_merge_round(v, 1);
            warp_merge_round(v, 2);
            warp_merge_round(v, 4);
            warp_merge_round(v, 8);
            if (lane < K)
                g_scratch[bb * K + lane] = select_lane(v, lane);
        }
    }

    // ================= arrival: every beam-block of the row, exactly once ======
    __syncthreads();
    if (tid == 0) {
        __threadfence();
        unsigned c = atomicAdd(&g_count[row], 1u);
        s_last = (c == BEAM - 1);
    }
    __syncthreads();
    if (!s_last) return;

    // ================= merge phase: last block of the row =================
    if (tid == 0) g_count[row] = 0u;         // reset for graph replay
    if (warp != 0) return;
    __threadfence();                          // acquire scratch writes

    bool kb = false; float mybias = 0.0f;
    if (lane < BEAM) {
        const int4 mm = ((const int4*)mask)[row * BEAM + lane];
        kb = (mm.x + mm.y + mm.z + mm.w) == NGRAM;
        mybias = (step == 0) ? 0.0f
                             : scores[(row * BEAM + lane) * STEPDIM + (step - 1)];
    }
    const unsigned ballot = __ballot_sync(0xffffffffu, kb) & 0xffu;

    ull v[K];
    const bool lvalid = (lane < BEAM) && !(step == 0 && lane != 0);
    if (lvalid && ((ballot >> lane) & 1u)) {
        #pragma unroll
        for (int q = 0; q < K; q++)
            v[q] = g_scratch[(row * BEAM + lane) * K + q];
    } else if (lvalid) {
        // Non-kept beam is constant (= bias): top-16 = first 16 indices.
        const unsigned ev = enc_f32(mybias);
        #pragma unroll
        for (int q = 0; q < K; q++)
            v[q] = make_key_enc(ev, (unsigned)lane * VOCAB + (unsigned)q);
    } else {
        #pragma unroll
        for (int q = 0; q < K; q++) v[q] = 0ull;
    }

    warp_merge_round(v, 1);
    warp_merge_round(v, 2);
    warp_merge_round(v, 4);
    warp_merge_round(v, 8);
    warp_merge_round(v, 16);
    // every lane holds the row's sorted top-16

    if (lane < K) {
        ull key = select_lane(v, lane);
        unsigned hi = (unsigned)(key >> 32);
        unsigned lo = (unsigned)key;
        unsigned u  = (hi & 0x80000000u) ? (hi ^ 0x80000000u) : ~hi;
        float val = __uint_as_float(u);
        unsigned flat = ~lo;
        unsigned bsel = flat / VOCAB;
        unsigned vsel = flat - bsel * VOCAB;

        out[              row * K + lane] = val;           // scores_buf
        out[BSZ * K     + row * K + lane] = (float)vsel;   // indices_buf
        out[2 * BSZ * K + row * K + lane] = (float)bsel;   // beams_buf
    }
}

extern "C" void kernel_launch(void* const* d_in, const int* in_sizes, int n_in,
                              void* d_out, int out_size) {
    (void)in_sizes; (void)out_size;
    const float* lprobs = (const float*)d_in[0];
    const float* scores = (const float*)d_in[1];
    const int*   mask   = (const int*)d_in[2];
    const int*   step   = (n_in > 3) ? (const int*)d_in[3] : nullptr;

    beam_topk<<<BSZ * BEAM, T>>>(lprobs, scores, mask, step, (float*)d_out);
}